// round 1
// baseline (speedup 1.0000x reference)
#include <cuda_runtime.h>
#include <cstdint>
#include <math.h>

#define NL    4
#define BATCH 2
#define SEQ   1024
#define DM    1024
#define DI    2048
#define DTR   64
#define NS    16
#define DC    4
#define MTOT  (BATCH*SEQ)   // 2048
#define KSPLIT 8

// ---------------- scratch (device globals; no allocation allowed) ----------
__device__ float g_x  [MTOT*DM];          // residual stream       8 MB
__device__ float g_ln [MTOT*DM];          // layernorm out         8 MB
__device__ float g_xz [MTOT*2*DI];        // in_proj out          32 MB
__device__ float g_xm [MTOT*DI];          // conv+silu out        16 MB
__device__ float g_dbcp[KSPLIT*MTOT*96];  // x_proj split-K parts  6 MB
__device__ float g_dbc[MTOT*96];          // x_proj out
__device__ float g_dt [MTOT*DI];          // dt (softplus'd)      16 MB
__device__ float g_y  [MTOT*DI];          // scan out             16 MB

// ---------------- small helpers -------------------------------------------
__device__ __forceinline__ float softplusf(float v) {
    return (v > 20.f) ? v : log1pf(__expf(v));
}

__global__ void copy_kernel(const float* __restrict__ a, float* __restrict__ o, int n) {
    int i = blockIdx.x * 256 + threadIdx.x;
    if (i < n) o[i] = a[i];
}

// ---------------- layernorm: one block per row of 1024 --------------------
__global__ __launch_bounds__(256)
void ln_kernel(const float* __restrict__ in, float* __restrict__ outp,
               const float* __restrict__ gw, const float* __restrict__ bw)
{
    int row = blockIdx.x;
    const float* xr = in + (size_t)row * DM;
    int t = threadIdx.x;
    float v[4]; float s = 0.f, s2 = 0.f;
#pragma unroll
    for (int i = 0; i < 4; i++) {
        v[i] = xr[t + i * 256];
        s += v[i];
        s2 = fmaf(v[i], v[i], s2);
    }
#pragma unroll
    for (int o = 16; o > 0; o >>= 1) {
        s  += __shfl_xor_sync(0xffffffffu, s,  o);
        s2 += __shfl_xor_sync(0xffffffffu, s2, o);
    }
    __shared__ float sh[16];
    if ((t & 31) == 0) { sh[t >> 5] = s; sh[(t >> 5) + 8] = s2; }
    __syncthreads();
    float S = 0.f, S2 = 0.f;
#pragma unroll
    for (int i = 0; i < 8; i++) { S += sh[i]; S2 += sh[i + 8]; }
    float mu  = S * (1.f / DM);
    float var = S2 * (1.f / DM) - mu * mu;
    float r   = rsqrtf(var + 1e-5f);
    float* orow = outp + (size_t)row * DM;
#pragma unroll
    for (int i = 0; i < 4; i++) {
        int c = t + i * 256;
        orow[c] = (v[i] - mu) * r * gw[c] + bw[c];
    }
}

// ---------------- causal depthwise conv (k=4) + SiLU ----------------------
__global__ __launch_bounds__(256)
void conv_silu(const float* __restrict__ xz, const float* __restrict__ cw,
               const float* __restrict__ cb, float* __restrict__ xmout)
{
    int d = blockIdx.x * 256 + threadIdx.x;   // 0..2047
    int l = blockIdx.y;
    int b = blockIdx.z;
    float acc = cb[d];
#pragma unroll
    for (int j = 0; j < DC; j++) {
        int lj = l - (DC - 1) + j;
        if (lj >= 0)
            acc = fmaf(cw[d * DC + j], xz[(size_t)(b * SEQ + lj) * (2 * DI) + d], acc);
    }
    float sv = acc / (1.f + __expf(-acc));    // silu
    xmout[(size_t)(b * SEQ + l) * DI + d] = sv;
}

// ---------------- reduce split-K partials for x_proj ----------------------
__global__ void reduce8(const float* __restrict__ part, float* __restrict__ outp)
{
    int i = blockIdx.x * 256 + threadIdx.x;   // < MTOT*96
    float s = 0.f;
#pragma unroll
    for (int k = 0; k < KSPLIT; k++) s += part[(size_t)k * (MTOT * 96) + i];
    outp[i] = s;
}

// ---------------- generic NT GEMM: C[m,n] = sum_k A[m,k]*B[n,k] -----------
// EPI: 0 = store, 1 = C += acc (residual add), 2 = softplus(acc + bias[n])
// gridDim.z > 1 => split-K: each z writes a full partial to C + z*M*N (EPI 0)
template<int BM, int BN, int BK, int TM, int TN, int EPI>
__global__ __launch_bounds__(256)
void gemm_nt(const float* __restrict__ A, const float* __restrict__ B,
             float* __restrict__ C, int M, int N, int K, int lda,
             const float* __restrict__ bias)
{
    __shared__ float As[BK][BM];
    __shared__ float Bs[BK][BN];
    const int tid = threadIdx.x;
    const int m0 = blockIdx.y * BM;
    const int n0 = blockIdx.x * BN;
    const int kper = K / gridDim.z;
    const int kbeg = blockIdx.z * kper;
    const int kend = kbeg + kper;
    if (gridDim.z > 1) C += (size_t)blockIdx.z * M * N;

    const int lr = tid >> 2;          // 0..63  (load row)
    const int lc = (tid & 3) << 2;    // 0,4,8,12 (load col, float4)

    constexpr int GM = TM / 4;        // row sub-groups of 4
    constexpr int GN = TN / 4;        // col sub-groups of 4
    const int rbase = (tid >> 4) * 4; // 0..60
    const int cbase = (tid & 15) * 4; // 0..60

    float acc[TM][TN];
#pragma unroll
    for (int i = 0; i < TM; i++)
#pragma unroll
        for (int j = 0; j < TN; j++) acc[i][j] = 0.f;

    for (int k0 = kbeg; k0 < kend; k0 += BK) {
#pragma unroll
        for (int r = 0; r < BM; r += 64) {
            const float* ap = A + (size_t)(m0 + lr + r) * lda + k0 + lc;
            float4 v = *(const float4*)ap;
            As[lc + 0][lr + r] = v.x; As[lc + 1][lr + r] = v.y;
            As[lc + 2][lr + r] = v.z; As[lc + 3][lr + r] = v.w;
        }
#pragma unroll
        for (int r = 0; r < BN; r += 64) {
            int nn = n0 + lr + r;
            float4 v = make_float4(0.f, 0.f, 0.f, 0.f);
            if (nn < N) v = *(const float4*)(B + (size_t)nn * K + k0 + lc);
            Bs[lc + 0][lr + r] = v.x; Bs[lc + 1][lr + r] = v.y;
            Bs[lc + 2][lr + r] = v.z; Bs[lc + 3][lr + r] = v.w;
        }
        __syncthreads();
#pragma unroll
        for (int kk = 0; kk < BK; kk++) {
            float a[TM], b[TN];
#pragma unroll
            for (int g = 0; g < GM; g++) {
                float4 v = *(const float4*)&As[kk][g * (BM / GM) + rbase];
                a[g * 4 + 0] = v.x; a[g * 4 + 1] = v.y;
                a[g * 4 + 2] = v.z; a[g * 4 + 3] = v.w;
            }
#pragma unroll
            for (int g = 0; g < GN; g++) {
                float4 v = *(const float4*)&Bs[kk][g * (BN / GN) + cbase];
                b[g * 4 + 0] = v.x; b[g * 4 + 1] = v.y;
                b[g * 4 + 2] = v.z; b[g * 4 + 3] = v.w;
            }
#pragma unroll
            for (int i = 0; i < TM; i++)
#pragma unroll
                for (int j = 0; j < TN; j++)
                    acc[i][j] = fmaf(a[i], b[j], acc[i][j]);
        }
        __syncthreads();
    }

    // epilogue (float4 stores; N is always a multiple of 4 here)
#pragma unroll
    for (int i = 0; i < TM; i++) {
        int gm = m0 + (i >> 2) * (BM / GM) + rbase + (i & 3);
#pragma unroll
        for (int g = 0; g < GN; g++) {
            int gn = n0 + g * (BN / GN) + cbase;
            if (gn < N) {
                float4 v;
                v.x = acc[i][g * 4 + 0]; v.y = acc[i][g * 4 + 1];
                v.z = acc[i][g * 4 + 2]; v.w = acc[i][g * 4 + 3];
                float* cp = C + (size_t)gm * N + gn;
                if (EPI == 1) {
                    float4 o = *(const float4*)cp;
                    v.x += o.x; v.y += o.y; v.z += o.z; v.w += o.w;
                } else if (EPI == 2) {
                    v.x = softplusf(v.x + bias[gn + 0]);
                    v.y = softplusf(v.y + bias[gn + 1]);
                    v.z = softplusf(v.z + bias[gn + 2]);
                    v.w = softplusf(v.w + bias[gn + 3]);
                }
                *(float4*)cp = v;
            }
        }
    }
}

// ---------------- selective scan ------------------------------------------
// thread = (s, d_local): 16 states x 16 d per 256-thread block.
// h_t = exp(dt*A) * h_{t-1} + dt*B_t*x_t ; y = sum_s h*C + x*D ; y *= silu(z)
__global__ __launch_bounds__(256)
void scan_kernel(const float* __restrict__ dt, const float* __restrict__ xm,
                 const float* __restrict__ xz, const float* __restrict__ dbc,
                 const float* __restrict__ A_log, const float* __restrict__ Dsk,
                 float* __restrict__ y)
{
    int t = threadIdx.x;
    int s = t & 15;
    int d = blockIdx.x * 16 + (t >> 4);
    int b = blockIdx.y;
    float A  = -__expf(A_log[d * NS + s]);
    float Dv = Dsk[d];
    float h  = 0.f;
    for (int l = 0; l < SEQ; l++) {
        int m = b * SEQ + l;
        float dtv = dt[(size_t)m * DI + d];
        float xv  = xm[(size_t)m * DI + d];
        float Bv  = dbc[m * 96 + DTR + s];
        float Cv  = dbc[m * 96 + DTR + NS + s];
        float dA  = __expf(dtv * A);
        h = fmaf(dA, h, dtv * xv * Bv);
        float p = h * Cv;
        // reduce over the 16 state lanes (stay inside each 16-lane group)
        p += __shfl_xor_sync(0xffffffffu, p, 1);
        p += __shfl_xor_sync(0xffffffffu, p, 2);
        p += __shfl_xor_sync(0xffffffffu, p, 4);
        p += __shfl_xor_sync(0xffffffffu, p, 8);
        if (s == 0) {
            float zv = xz[(size_t)m * (2 * DI) + DI + d];
            float yv = p + xv * Dv;
            yv *= zv / (1.f + __expf(-zv));   // * silu(z)
            y[(size_t)m * DI + d] = yv;
        }
    }
}

// ---------------- driver ---------------------------------------------------
extern "C" void kernel_launch(void* const* d_in, const int* in_sizes, int n_in,
                              void* d_out, int out_size)
{
    const float* x_in   = (const float*)d_in[0];
    const float* in_w   = (const float*)d_in[1];
    const float* conv_w = (const float*)d_in[2];
    const float* conv_b = (const float*)d_in[3];
    const float* xp_w   = (const float*)d_in[4];
    const float* dt_w   = (const float*)d_in[5];
    const float* dt_b   = (const float*)d_in[6];
    const float* A_log  = (const float*)d_in[7];
    const float* D_sk   = (const float*)d_in[8];
    const float* out_w  = (const float*)d_in[9];
    const float* ln_g   = (const float*)d_in[10];
    const float* ln_b   = (const float*)d_in[11];
    float* out = (float*)d_out;

    float *px, *pln, *pxz, *pxm, *pdbcp, *pdbc, *pdt, *py;
    cudaGetSymbolAddress((void**)&px,    g_x);
    cudaGetSymbolAddress((void**)&pln,   g_ln);
    cudaGetSymbolAddress((void**)&pxz,   g_xz);
    cudaGetSymbolAddress((void**)&pxm,   g_xm);
    cudaGetSymbolAddress((void**)&pdbcp, g_dbcp);
    cudaGetSymbolAddress((void**)&pdbc,  g_dbc);
    cudaGetSymbolAddress((void**)&pdt,   g_dt);
    cudaGetSymbolAddress((void**)&py,    g_y);

    copy_kernel<<<(MTOT * DM) / 256, 256>>>(x_in, px, MTOT * DM);

    for (int i = 0; i < NL; i++) {
        // layernorm
        ln_kernel<<<MTOT, 256>>>(px, pln, ln_g, ln_b);
        // in_proj: [2048,1024] x [4096,1024]^T -> [2048,4096]
        gemm_nt<128, 128, 16, 8, 8, 0><<<dim3((2 * DI) / 128, MTOT / 128, 1), 256>>>(
            pln, in_w + (size_t)i * 2 * DI * DM, pxz, MTOT, 2 * DI, DM, DM, nullptr);
        // depthwise conv + silu
        conv_silu<<<dim3(DI / 256, SEQ, BATCH), 256>>>(
            pxz, conv_w + (size_t)i * DI * DC, conv_b + (size_t)i * DI, pxm);
        // x_proj (skinny N=96): split-K into 8 partials, then reduce
        gemm_nt<64, 128, 16, 4, 8, 0><<<dim3(1, MTOT / 64, KSPLIT), 256>>>(
            pxm, xp_w + (size_t)i * 96 * DI, pdbcp, MTOT, 96, DI, DI, nullptr);
        reduce8<<<(MTOT * 96) / 256, 256>>>(pdbcp, pdbc);
        // dt_proj + bias + softplus: [2048,64] x [2048,64]^T -> [2048,2048]
        gemm_nt<128, 128, 16, 8, 8, 2><<<dim3(DI / 128, MTOT / 128, 1), 256>>>(
            pdbc, dt_w + (size_t)i * DI * DTR, pdt, MTOT, DI, DTR, 96,
            dt_b + (size_t)i * DI);
        // selective scan (+ D skip + silu(z) gate)
        scan_kernel<<<dim3(DI / 16, BATCH), 256>>>(
            pdt, pxm, pxz, pdbc, A_log + (size_t)i * DI * NS,
            D_sk + (size_t)i * DI, py);
        // out_proj accumulated into residual: x += y @ out_w^T
        gemm_nt<128, 128, 16, 8, 8, 1><<<dim3(DM / 128, MTOT / 128, 1), 256>>>(
            py, out_w + (size_t)i * DM * DI, px, MTOT, DM, DI, DI, nullptr);
    }

    // final layernorm straight into d_out
    ln_kernel<<<MTOT, 256>>>(px, out, ln_g, ln_b);
}

// round 5
// speedup vs baseline: 1.0686x; 1.0686x over previous
#include <cuda_runtime.h>
#include <cstdint>
#include <math.h>

#define NL    4
#define BATCH 2
#define SEQ   1024
#define DM    1024
#define DI    2048
#define DTR   64
#define NS    16
#define DC    4
#define MTOT  (BATCH*SEQ)   // 2048
#define KSPLIT 8

// ---------------- scratch (device globals; no allocation allowed) ----------
__device__ float g_x  [MTOT*DM];
__device__ float g_ln [MTOT*DM];
__device__ float g_xz [MTOT*2*DI];
__device__ float g_xm [MTOT*DI];
__device__ float g_dbcp[KSPLIT*MTOT*96];
__device__ float g_dbc[MTOT*96];
__device__ float g_dt [MTOT*DI];
__device__ float g_y  [MTOT*DI];

// ---------------- f32x2 packed-FMA helpers --------------------------------
#define PACK2(dst, s)  asm("mov.b64 %0, {%1, %1};" : "=l"(dst) : "f"(s))
#define FFMA2(c, a, b) asm("fma.rn.f32x2 %0, %1, %2, %0;" : "+l"(c) : "l"(a), "l"(b))

__device__ __forceinline__ float2 unpack2(unsigned long long v) {
    float2 f;
    asm("mov.b64 {%0, %1}, %2;" : "=f"(f.x), "=f"(f.y) : "l"(v));
    return f;
}

__device__ __forceinline__ float softplusf(float v) {
    return (v > 20.f) ? v : log1pf(__expf(v));
}

__global__ void copy_kernel(const float* __restrict__ a, float* __restrict__ o, int n) {
    int i = blockIdx.x * 256 + threadIdx.x;
    if (i < n) o[i] = a[i];
}

// ---------------- layernorm: one block per row of 1024 --------------------
__global__ __launch_bounds__(256)
void ln_kernel(const float* __restrict__ in, float* __restrict__ outp,
               const float* __restrict__ gw, const float* __restrict__ bw)
{
    int row = blockIdx.x;
    const float* xr = in + (size_t)row * DM;
    int t = threadIdx.x;
    float v[4]; float s = 0.f, s2 = 0.f;
#pragma unroll
    for (int i = 0; i < 4; i++) {
        v[i] = xr[t + i * 256];
        s += v[i];
        s2 = fmaf(v[i], v[i], s2);
    }
#pragma unroll
    for (int o = 16; o > 0; o >>= 1) {
        s  += __shfl_xor_sync(0xffffffffu, s,  o);
        s2 += __shfl_xor_sync(0xffffffffu, s2, o);
    }
    __shared__ float sh[16];
    if ((t & 31) == 0) { sh[t >> 5] = s; sh[(t >> 5) + 8] = s2; }
    __syncthreads();
    float S = 0.f, S2 = 0.f;
#pragma unroll
    for (int i = 0; i < 8; i++) { S += sh[i]; S2 += sh[i + 8]; }
    float mu  = S * (1.f / DM);
    float var = S2 * (1.f / DM) - mu * mu;
    float r   = rsqrtf(var + 1e-5f);
    float* orow = outp + (size_t)row * DM;
#pragma unroll
    for (int i = 0; i < 4; i++) {
        int c = t + i * 256;
        orow[c] = (v[i] - mu) * r * gw[c] + bw[c];
    }
}

// ---------------- causal depthwise conv (k=4) + SiLU ----------------------
__global__ __launch_bounds__(256)
void conv_silu(const float* __restrict__ xz, const float* __restrict__ cw,
               const float* __restrict__ cb, float* __restrict__ xmout)
{
    int d = blockIdx.x * 256 + threadIdx.x;
    int l = blockIdx.y;
    int b = blockIdx.z;
    float acc = cb[d];
#pragma unroll
    for (int j = 0; j < DC; j++) {
        int lj = l - (DC - 1) + j;
        if (lj >= 0)
            acc = fmaf(cw[d * DC + j], xz[(size_t)(b * SEQ + lj) * (2 * DI) + d], acc);
    }
    float sv = acc / (1.f + __expf(-acc));
    xmout[(size_t)(b * SEQ + l) * DI + d] = sv;
}

// ---------------- reduce split-K partials for x_proj ----------------------
__global__ void reduce8(const float* __restrict__ part, float* __restrict__ outp)
{
    int i = blockIdx.x * 256 + threadIdx.x;
    float s = 0.f;
#pragma unroll
    for (int k = 0; k < KSPLIT; k++) s += part[(size_t)k * (MTOT * 96) + i];
    outp[i] = s;
}

// ---------------- NT GEMM with packed f32x2 FMAs --------------------------
// C[m,n] = sum_k A[m,k]*B[n,k].  Fixed tile: BM=BN=128, BK=16, 256 thr, 8x8.
// EPI: 0 = store, 1 = C += acc, 2 = softplus(acc + bias[n])
// gridDim.z > 1 => split-K: each z writes a full partial to C + z*M*N (EPI 0)
template<int EPI>
__global__ __launch_bounds__(256, 2)
void gemm_nt(const float* __restrict__ A, const float* __restrict__ B,
             float* __restrict__ C, int M, int N, int K, int lda,
             const float* __restrict__ bias)
{
    constexpr int BM = 128, BN = 128, BK = 16;
    __shared__ float As[BK][BM];
    __shared__ float Bs[BK][BN];
    const int tid = threadIdx.x;
    const int m0 = blockIdx.y * BM;
    const int n0 = blockIdx.x * BN;
    const int kper = K / gridDim.z;
    const int kbeg = blockIdx.z * kper;
    const int kend = kbeg + kper;
    if (gridDim.z > 1) C += (size_t)blockIdx.z * M * N;

    const int lr = tid >> 2;          // 0..63
    const int lc = (tid & 3) << 2;    // 0,4,8,12
    const int rbase = (tid >> 4) * 4; // 0..60
    const int cbase = (tid & 15) * 4; // 0..60

    // acc[i][j2]: i = M-row (8), j2 = packed N-pair (4)
    unsigned long long acc[8][4];
#pragma unroll
    for (int i = 0; i < 8; i++)
#pragma unroll
        for (int j = 0; j < 4; j++) acc[i][j] = 0ull;

    for (int k0 = kbeg; k0 < kend; k0 += BK) {
#pragma unroll
        for (int r = 0; r < BM; r += 64) {
            const float* ap = A + (size_t)(m0 + lr + r) * lda + k0 + lc;
            float4 v = *(const float4*)ap;
            As[lc + 0][lr + r] = v.x; As[lc + 1][lr + r] = v.y;
            As[lc + 2][lr + r] = v.z; As[lc + 3][lr + r] = v.w;
        }
#pragma unroll
        for (int r = 0; r < BN; r += 64) {
            int nn = n0 + lr + r;
            float4 v = make_float4(0.f, 0.f, 0.f, 0.f);
            if (nn < N) v = *(const float4*)(B + (size_t)nn * K + k0 + lc);
            Bs[lc + 0][lr + r] = v.x; Bs[lc + 1][lr + r] = v.y;
            Bs[lc + 2][lr + r] = v.z; Bs[lc + 3][lr + r] = v.w;
        }
        __syncthreads();
#pragma unroll
        for (int kk = 0; kk < BK; kk++) {
            float4 av0 = *(const float4*)&As[kk][rbase];
            float4 av1 = *(const float4*)&As[kk][64 + rbase];
            ulonglong2 bv0 = *(const ulonglong2*)&Bs[kk][cbase];
            ulonglong2 bv1 = *(const ulonglong2*)&Bs[kk][64 + cbase];
            unsigned long long bb[4];
            bb[0] = bv0.x; bb[1] = bv0.y; bb[2] = bv1.x; bb[3] = bv1.y;
            unsigned long long a2[8];
            PACK2(a2[0], av0.x); PACK2(a2[1], av0.y);
            PACK2(a2[2], av0.z); PACK2(a2[3], av0.w);
            PACK2(a2[4], av1.x); PACK2(a2[5], av1.y);
            PACK2(a2[6], av1.z); PACK2(a2[7], av1.w);
#pragma unroll
            for (int i = 0; i < 8; i++)
#pragma unroll
                for (int j = 0; j < 4; j++)
                    FFMA2(acc[i][j], a2[i], bb[j]);
        }
        __syncthreads();
    }

    // epilogue
#pragma unroll
    for (int i = 0; i < 8; i++) {
        int gm = m0 + (i >> 2) * 64 + rbase + (i & 3);
#pragma unroll
        for (int g = 0; g < 2; g++) {
            int gn = n0 + g * 64 + cbase;
            if (gn < N) {
                float2 p0 = unpack2(acc[i][g * 2 + 0]);
                float2 p1 = unpack2(acc[i][g * 2 + 1]);
                float4 v = make_float4(p0.x, p0.y, p1.x, p1.y);
                float* cp = C + (size_t)gm * N + gn;
                if (EPI == 1) {
                    float4 o = *(const float4*)cp;
                    v.x += o.x; v.y += o.y; v.z += o.z; v.w += o.w;
                } else if (EPI == 2) {
                    v.x = softplusf(v.x + bias[gn + 0]);
                    v.y = softplusf(v.y + bias[gn + 1]);
                    v.z = softplusf(v.z + bias[gn + 2]);
                    v.w = softplusf(v.w + bias[gn + 3]);
                }
                *(float4*)cp = v;
            }
        }
    }
}

// ---------------- selective scan ------------------------------------------
__global__ __launch_bounds__(256)
void scan_kernel(const float* __restrict__ dt, const float* __restrict__ xm,
                 const float* __restrict__ xz, const float* __restrict__ dbc,
                 const float* __restrict__ A_log, const float* __restrict__ Dsk,
                 float* __restrict__ y)
{
    int t = threadIdx.x;
    int s = t & 15;
    int d = blockIdx.x * 16 + (t >> 4);
    int b = blockIdx.y;
    float A  = -__expf(A_log[d * NS + s]);
    float Dv = Dsk[d];
    float h  = 0.f;
    for (int l = 0; l < SEQ; l++) {
        int m = b * SEQ + l;
        float dtv = dt[(size_t)m * DI + d];
        float xv  = xm[(size_t)m * DI + d];
        float Bv  = dbc[m * 96 + DTR + s];
        float Cv  = dbc[m * 96 + DTR + NS + s];
        float dA  = __expf(dtv * A);
        h = fmaf(dA, h, dtv * xv * Bv);
        float p = h * Cv;
        p += __shfl_xor_sync(0xffffffffu, p, 1);
        p += __shfl_xor_sync(0xffffffffu, p, 2);
        p += __shfl_xor_sync(0xffffffffu, p, 4);
        p += __shfl_xor_sync(0xffffffffu, p, 8);
        if (s == 0) {
            float zv = xz[(size_t)m * (2 * DI) + DI + d];
            float yv = p + xv * Dv;
            yv *= zv / (1.f + __expf(-zv));
            y[(size_t)m * DI + d] = yv;
        }
    }
}

// ---------------- driver ---------------------------------------------------
extern "C" void kernel_launch(void* const* d_in, const int* in_sizes, int n_in,
                              void* d_out, int out_size)
{
    const float* x_in   = (const float*)d_in[0];
    const float* in_w   = (const float*)d_in[1];
    const float* conv_w = (const float*)d_in[2];
    const float* conv_b = (const float*)d_in[3];
    const float* xp_w   = (const float*)d_in[4];
    const float* dt_w   = (const float*)d_in[5];
    const float* dt_b   = (const float*)d_in[6];
    const float* A_log  = (const float*)d_in[7];
    const float* D_sk   = (const float*)d_in[8];
    const float* out_w  = (const float*)d_in[9];
    const float* ln_g   = (const float*)d_in[10];
    const float* ln_b   = (const float*)d_in[11];
    float* out = (float*)d_out;

    float *px, *pln, *pxz, *pxm, *pdbcp, *pdbc, *pdt, *py;
    cudaGetSymbolAddress((void**)&px,    g_x);
    cudaGetSymbolAddress((void**)&pln,   g_ln);
    cudaGetSymbolAddress((void**)&pxz,   g_xz);
    cudaGetSymbolAddress((void**)&pxm,   g_xm);
    cudaGetSymbolAddress((void**)&pdbcp, g_dbcp);
    cudaGetSymbolAddress((void**)&pdbc,  g_dbc);
    cudaGetSymbolAddress((void**)&pdt,   g_dt);
    cudaGetSymbolAddress((void**)&py,    g_y);

    copy_kernel<<<(MTOT * DM) / 256, 256>>>(x_in, px, MTOT * DM);

    for (int i = 0; i < NL; i++) {
        ln_kernel<<<MTOT, 256>>>(px, pln, ln_g, ln_b);
        // in_proj: [2048,1024] x [4096,1024]^T -> [2048,4096]
        gemm_nt<0><<<dim3((2 * DI) / 128, MTOT / 128, 1), 256>>>(
            pln, in_w + (size_t)i * 2 * DI * DM, pxz, MTOT, 2 * DI, DM, DM, nullptr);
        conv_silu<<<dim3(DI / 256, SEQ, BATCH), 256>>>(
            pxz, conv_w + (size_t)i * DI * DC, conv_b + (size_t)i * DI, pxm);
        // x_proj (skinny N=96): split-K into 8 partials, then reduce
        gemm_nt<0><<<dim3(1, MTOT / 128, KSPLIT), 256>>>(
            pxm, xp_w + (size_t)i * 96 * DI, pdbcp, MTOT, 96, DI, DI, nullptr);
        reduce8<<<(MTOT * 96) / 256, 256>>>(pdbcp, pdbc);
        // dt_proj + bias + softplus
        gemm_nt<2><<<dim3(DI / 128, MTOT / 128, 1), 256>>>(
            pdbc, dt_w + (size_t)i * DI * DTR, pdt, MTOT, DI, DTR, 96,
            dt_b + (size_t)i * DI);
        scan_kernel<<<dim3(DI / 16, BATCH), 256>>>(
            pdt, pxm, pxz, pdbc, A_log + (size_t)i * DI * NS,
            D_sk + (size_t)i * DI, py);
        // out_proj accumulated into residual
        gemm_nt<1><<<dim3(DM / 128, MTOT / 128, 1), 256>>>(
            py, out_w + (size_t)i * DM * DI, px, MTOT, DM, DI, DI, nullptr);
    }

    ln_kernel<<<MTOT, 256>>>(px, out, ln_g, ln_b);
}

// round 7
// speedup vs baseline: 1.1747x; 1.0993x over previous
#include <cuda_runtime.h>
#include <cuda_bf16.h>
#include <cstdint>
#include <math.h>

#define NL    4
#define BATCH 2
#define SEQ   1024
#define DM    1024
#define DI    2048
#define DTR   64
#define NS    16
#define DC    4
#define MTOT  (BATCH*SEQ)   // 2048
#define KSPLIT 8

typedef __nv_bfloat16 bf16;

// ---------------- scratch (device globals; no allocation allowed) ----------
__device__ float g_x  [MTOT*DM];
__device__ float g_xz [MTOT*2*DI];
__device__ float g_xm [MTOT*DI];
__device__ float g_dbcp[KSPLIT*MTOT*96];
__device__ float g_dbc[MTOT*96];
__device__ float g_dt [MTOT*DI];

__device__ __align__(128) bf16 g_lnh[MTOT*DM];
__device__ __align__(128) bf16 g_lnl[MTOT*DM];
__device__ __align__(128) bf16 g_xmh[MTOT*DI];
__device__ __align__(128) bf16 g_xml[MTOT*DI];
__device__ __align__(128) bf16 g_dbch[MTOT*96];
__device__ __align__(128) bf16 g_dbcl[MTOT*96];
__device__ __align__(128) bf16 g_yh [MTOT*DI];
__device__ __align__(128) bf16 g_yl [MTOT*DI];
__device__ __align__(128) bf16 w_inh [NL*2*DI*DM];
__device__ __align__(128) bf16 w_inl [NL*2*DI*DM];
__device__ __align__(128) bf16 w_xph [NL*96*DI];
__device__ __align__(128) bf16 w_xpl [NL*96*DI];
__device__ __align__(128) bf16 w_dth [NL*DI*DTR];
__device__ __align__(128) bf16 w_dtl [NL*DI*DTR];
__device__ __align__(128) bf16 w_outh[NL*DM*DI];
__device__ __align__(128) bf16 w_outl[NL*DM*DI];

// ---------------- helpers --------------------------------------------------
__device__ __forceinline__ uint32_t smem_u32(const void* p) {
    uint32_t a;
    asm("{ .reg .u64 t; cvta.to.shared.u64 t, %1; cvt.u32.u64 %0, t; }"
        : "=r"(a) : "l"(p));
    return a;
}
#define SW(x) ((x) ^ (((x) >> 3) & 0x70))

__device__ __forceinline__ void ldsm4(uint32_t* d, uint32_t addr) {
    asm volatile("ldmatrix.sync.aligned.m8n8.x4.shared.b16 {%0,%1,%2,%3}, [%4];"
        : "=r"(d[0]), "=r"(d[1]), "=r"(d[2]), "=r"(d[3]) : "r"(addr));
}
__device__ __forceinline__ void mma16816(float* c, const uint32_t* a,
                                         uint32_t b0, uint32_t b1) {
    asm volatile(
        "mma.sync.aligned.m16n8k16.row.col.f32.bf16.bf16.f32 "
        "{%0,%1,%2,%3}, {%4,%5,%6,%7}, {%8,%9}, {%0,%1,%2,%3};"
        : "+f"(c[0]), "+f"(c[1]), "+f"(c[2]), "+f"(c[3])
        : "r"(a[0]), "r"(a[1]), "r"(a[2]), "r"(a[3]), "r"(b0), "r"(b1));
}

__device__ __forceinline__ float softplusf(float v) {
    return (v > 20.f) ? v : log1pf(__expf(v));
}
__device__ __forceinline__ void split_bf16(float v, bf16* hp, bf16* lp) {
    bf16 h = __float2bfloat16(v);
    *hp = h;
    *lp = __float2bfloat16(v - __bfloat162float(h));
}

// ---------------- misc kernels --------------------------------------------
__global__ void copy_kernel(const float* __restrict__ a, float* __restrict__ o, int n) {
    int i = blockIdx.x * 256 + threadIdx.x;
    if (i < n) o[i] = a[i];
}
__global__ void cvt_w(const float* __restrict__ src, bf16* __restrict__ hi,
                      bf16* __restrict__ lo, int n) {
    int i = blockIdx.x * 256 + threadIdx.x;
    if (i < n) split_bf16(src[i], hi + i, lo + i);
}

// ---------------- layernorm -----------------------------------------------
template<int BF>
__global__ __launch_bounds__(256)
void ln_kernel(const float* __restrict__ in, float* __restrict__ outp,
               bf16* __restrict__ oh, bf16* __restrict__ ol,
               const float* __restrict__ gw, const float* __restrict__ bw)
{
    int row = blockIdx.x;
    const float* xr = in + (size_t)row * DM;
    int t = threadIdx.x;
    float v[4]; float s = 0.f, s2 = 0.f;
#pragma unroll
    for (int i = 0; i < 4; i++) {
        v[i] = xr[t + i * 256];
        s += v[i];
        s2 = fmaf(v[i], v[i], s2);
    }
#pragma unroll
    for (int o = 16; o > 0; o >>= 1) {
        s  += __shfl_xor_sync(0xffffffffu, s,  o);
        s2 += __shfl_xor_sync(0xffffffffu, s2, o);
    }
    __shared__ float sh[16];
    if ((t & 31) == 0) { sh[t >> 5] = s; sh[(t >> 5) + 8] = s2; }
    __syncthreads();
    float S = 0.f, S2 = 0.f;
#pragma unroll
    for (int i = 0; i < 8; i++) { S += sh[i]; S2 += sh[i + 8]; }
    float mu  = S * (1.f / DM);
    float var = S2 * (1.f / DM) - mu * mu;
    float r   = rsqrtf(var + 1e-5f);
#pragma unroll
    for (int i = 0; i < 4; i++) {
        int c = t + i * 256;
        float val = (v[i] - mu) * r * gw[c] + bw[c];
        if (BF) split_bf16(val, oh + (size_t)row * DM + c, ol + (size_t)row * DM + c);
        else    outp[(size_t)row * DM + c] = val;
    }
}

// ---------------- causal depthwise conv (k=4) + SiLU + bf16 split ---------
__global__ __launch_bounds__(256)
void conv_silu(const float* __restrict__ xz, const float* __restrict__ cw,
               const float* __restrict__ cb, float* __restrict__ xmout,
               bf16* __restrict__ oh, bf16* __restrict__ ol)
{
    int d = blockIdx.x * 256 + threadIdx.x;
    int l = blockIdx.y;
    int b = blockIdx.z;
    float acc = cb[d];
#pragma unroll
    for (int j = 0; j < DC; j++) {
        int lj = l - (DC - 1) + j;
        if (lj >= 0)
            acc = fmaf(cw[d * DC + j], xz[(size_t)(b * SEQ + lj) * (2 * DI) + d], acc);
    }
    float sv = acc / (1.f + __expf(-acc));
    size_t o = (size_t)(b * SEQ + l) * DI + d;
    xmout[o] = sv;
    split_bf16(sv, oh + o, ol + o);
}

// ---------------- reduce split-K partials + bf16 split --------------------
__global__ void reduce8(const float* __restrict__ part, float* __restrict__ outp,
                        bf16* __restrict__ oh, bf16* __restrict__ ol)
{
    int i = blockIdx.x * 256 + threadIdx.x;
    float s = 0.f;
#pragma unroll
    for (int k = 0; k < KSPLIT; k++) s += part[(size_t)k * (MTOT * 96) + i];
    outp[i] = s;
    split_bf16(s, oh + i, ol + i);
}

// ---------------- 3xBF16-split GEMM on mma.sync (HMMA) --------------------
// C[m,n] = sum_k A[m,k]*B[n,k], A=Ah+Al, B=Bh+Bl, terms ah*bh + ah*bl + al*bh.
// Block 128x128, 8 warps (2m x 4n), warp tile 64x32, BK=64 single-buffered.
// EPI: 0 = store, 1 = C += acc, 2 = softplus(acc + bias[n])
// gridDim.z > 1 => split-K: z handles K-chunk [z*K,(z+1)*K), writes C + z*M*N.
#define SMEM_GEMM 65536
template<int EPI>
__global__ __launch_bounds__(256, 2)
void gemm3bf(const bf16* __restrict__ Ah, const bf16* __restrict__ Al, int lda,
             const bf16* __restrict__ Bh, const bf16* __restrict__ Bl, int ldb,
             float* __restrict__ C, int M, int N, int K,
             const float* __restrict__ bias)
{
    extern __shared__ char smem[];
    const uint32_t sb = smem_u32(smem);
    constexpr int SA_H = 0, SA_L = 16384, SB_H = 32768, SB_L = 49152;
    const int tid = threadIdx.x, wid = tid >> 5, lane = tid & 31;
    const int m0 = blockIdx.y * 128, n0 = blockIdx.x * 128;
    const long kbeg = (long)blockIdx.z * K;
    if (gridDim.z > 1) C += (size_t)blockIdx.z * M * N;

    const int wm = wid >> 2, wn = wid & 3;   // warp tile origin (64m x 32n)

    // stage loaders: thread (r,h) loads 64B of row r, half h, per array
    const int r = tid >> 1, h = tid & 1;
    const size_t aoff = (size_t)(m0 + r) * lda + kbeg + h * 32;
    const size_t boff = (size_t)(n0 + r) * ldb + kbeg + h * 32;
    const bool bok = (n0 + r) < N;
    const uint32_t st = (uint32_t)(r * 128 + h * 64);

    // ldmatrix per-lane address pieces
    const int g = lane >> 3, r8 = lane & 7;
    const int arow = wm * 64 + (g & 1) * 8 + r8;   // + mt*16
    const int brow = wn * 32 + (g & 1) * 8 + r8;   // + np*16
    const int khalf = (g >> 1) * 16;               // + kc*32

    float acc[4][4][4];
#pragma unroll
    for (int i = 0; i < 4; i++)
#pragma unroll
        for (int j = 0; j < 4; j++)
#pragma unroll
            for (int q = 0; q < 4; q++) acc[i][j][q] = 0.f;

    const int S = K / 64;
    for (int s = 0; s < S; s++) {
#pragma unroll
        for (int i = 0; i < 4; i++) {
            uint32_t sw = SW(st + i * 16);
            size_t ge = (size_t)s * 64 + i * 8;
            *(uint4*)(smem + SA_H + sw) = *(const uint4*)(Ah + aoff + ge);
            *(uint4*)(smem + SA_L + sw) = *(const uint4*)(Al + aoff + ge);
            uint4 z4 = make_uint4(0, 0, 0, 0);
            *(uint4*)(smem + SB_H + sw) = bok ? *(const uint4*)(Bh + boff + ge) : z4;
            *(uint4*)(smem + SB_L + sw) = bok ? *(const uint4*)(Bl + boff + ge) : z4;
        }
        __syncthreads();

#pragma unroll
        for (int kc = 0; kc < 4; kc++) {
            uint32_t ah[4][4], al[4][4];
#pragma unroll
            for (int mt = 0; mt < 4; mt++) {
                uint32_t off = SW((uint32_t)((arow + mt * 16) * 128 + kc * 32 + khalf));
                ldsm4(ah[mt], sb + SA_H + off);
                ldsm4(al[mt], sb + SA_L + off);
            }
#pragma unroll
            for (int np = 0; np < 2; np++) {
                uint32_t boffs = SW((uint32_t)((brow + np * 16) * 128 + kc * 32 + khalf));
                uint32_t bh4[4], bl4[4];
                ldsm4(bh4, sb + SB_H + boffs);
                ldsm4(bl4, sb + SB_L + boffs);
#pragma unroll
                for (int mt = 0; mt < 4; mt++) {
                    mma16816(acc[mt][np * 2],     ah[mt], bh4[0], bh4[2]);
                    mma16816(acc[mt][np * 2],     ah[mt], bl4[0], bl4[2]);
                    mma16816(acc[mt][np * 2],     al[mt], bh4[0], bh4[2]);
                    mma16816(acc[mt][np * 2 + 1], ah[mt], bh4[1], bh4[3]);
                    mma16816(acc[mt][np * 2 + 1], ah[mt], bl4[1], bl4[3]);
                    mma16816(acc[mt][np * 2 + 1], al[mt], bh4[1], bh4[3]);
                }
            }
        }
        __syncthreads();
    }

    // epilogue
    const int gid = lane >> 2, tg = lane & 3;
#pragma unroll
    for (int mt = 0; mt < 4; mt++) {
#pragma unroll
        for (int nt = 0; nt < 4; nt++) {
            int gn = n0 + wn * 32 + nt * 8 + tg * 2;
            if (gn < N) {
                int gm = m0 + wm * 64 + mt * 16 + gid;
                float* cp0 = C + (size_t)gm * N + gn;
                float* cp1 = C + (size_t)(gm + 8) * N + gn;
                float2 v0 = make_float2(acc[mt][nt][0], acc[mt][nt][1]);
                float2 v1 = make_float2(acc[mt][nt][2], acc[mt][nt][3]);
                if (EPI == 1) {
                    float2 o0 = *(const float2*)cp0, o1 = *(const float2*)cp1;
                    v0.x += o0.x; v0.y += o0.y; v1.x += o1.x; v1.y += o1.y;
                } else if (EPI == 2) {
                    float b0 = bias[gn], b1 = bias[gn + 1];
                    v0.x = softplusf(v0.x + b0); v0.y = softplusf(v0.y + b1);
                    v1.x = softplusf(v1.x + b0); v1.y = softplusf(v1.y + b1);
                }
                *(float2*)cp0 = v0;
                *(float2*)cp1 = v1;
            }
        }
    }
}

// ---------------- selective scan (writes bf16 hi/lo of y) -----------------
__global__ __launch_bounds__(256)
void scan_kernel(const float* __restrict__ dt, const float* __restrict__ xm,
                 const float* __restrict__ xz, const float* __restrict__ dbc,
                 const float* __restrict__ A_log, const float* __restrict__ Dsk,
                 bf16* __restrict__ yh, bf16* __restrict__ yl)
{
    int t = threadIdx.x;
    int s = t & 15;
    int d = blockIdx.x * 16 + (t >> 4);
    int b = blockIdx.y;
    float A  = -__expf(A_log[d * NS + s]);
    float Dv = Dsk[d];
    float h  = 0.f;
    for (int l = 0; l < SEQ; l++) {
        int m = b * SEQ + l;
        float dtv = dt[(size_t)m * DI + d];
        float xv  = xm[(size_t)m * DI + d];
        float Bv  = dbc[m * 96 + DTR + s];
        float Cv  = dbc[m * 96 + DTR + NS + s];
        float dA  = __expf(dtv * A);
        h = fmaf(dA, h, dtv * xv * Bv);
        float p = h * Cv;
        p += __shfl_xor_sync(0xffffffffu, p, 1);
        p += __shfl_xor_sync(0xffffffffu, p, 2);
        p += __shfl_xor_sync(0xffffffffu, p, 4);
        p += __shfl_xor_sync(0xffffffffu, p, 8);
        if (s == 0) {
            float zv = xz[(size_t)m * (2 * DI) + DI + d];
            float yv = p + xv * Dv;
            yv *= zv / (1.f + __expf(-zv));
            split_bf16(yv, yh + (size_t)m * DI + d, yl + (size_t)m * DI + d);
        }
    }
}

// ---------------- driver ---------------------------------------------------
extern "C" void kernel_launch(void* const* d_in, const int* in_sizes, int n_in,
                              void* d_out, int out_size)
{
    const float* x_in   = (const float*)d_in[0];
    const float* in_w   = (const float*)d_in[1];
    const float* conv_w = (const float*)d_in[2];
    const float* conv_b = (const float*)d_in[3];
    const float* xp_w   = (const float*)d_in[4];
    const float* dt_w   = (const float*)d_in[5];
    const float* dt_b   = (const float*)d_in[6];
    const float* A_log  = (const float*)d_in[7];
    const float* D_sk   = (const float*)d_in[8];
    const float* out_w  = (const float*)d_in[9];
    const float* ln_g   = (const float*)d_in[10];
    const float* ln_b   = (const float*)d_in[11];
    float* out = (float*)d_out;

    float *px, *pxz, *pxm, *pdbcp, *pdbc, *pdt;
    bf16 *plnh, *plnl, *pxmh, *pxml, *pdbch, *pdbcl, *pyh, *pyl;
    bf16 *pwinh, *pwinl, *pwxph, *pwxpl, *pwdth, *pwdtl, *pwoh, *pwol;
    cudaGetSymbolAddress((void**)&px,    g_x);
    cudaGetSymbolAddress((void**)&pxz,   g_xz);
    cudaGetSymbolAddress((void**)&pxm,   g_xm);
    cudaGetSymbolAddress((void**)&pdbcp, g_dbcp);
    cudaGetSymbolAddress((void**)&pdbc,  g_dbc);
    cudaGetSymbolAddress((void**)&pdt,   g_dt);
    cudaGetSymbolAddress((void**)&plnh,  g_lnh);
    cudaGetSymbolAddress((void**)&plnl,  g_lnl);
    cudaGetSymbolAddress((void**)&pxmh,  g_xmh);
    cudaGetSymbolAddress((void**)&pxml,  g_xml);
    cudaGetSymbolAddress((void**)&pdbch, g_dbch);
    cudaGetSymbolAddress((void**)&pdbcl, g_dbcl);
    cudaGetSymbolAddress((void**)&pyh,   g_yh);
    cudaGetSymbolAddress((void**)&pyl,   g_yl);
    cudaGetSymbolAddress((void**)&pwinh, w_inh);
    cudaGetSymbolAddress((void**)&pwinl, w_inl);
    cudaGetSymbolAddress((void**)&pwxph, w_xph);
    cudaGetSymbolAddress((void**)&pwxpl, w_xpl);
    cudaGetSymbolAddress((void**)&pwdth, w_dth);
    cudaGetSymbolAddress((void**)&pwdtl, w_dtl);
    cudaGetSymbolAddress((void**)&pwoh,  w_outh);
    cudaGetSymbolAddress((void**)&pwol,  w_outl);

    cudaFuncSetAttribute(gemm3bf<0>, cudaFuncAttributeMaxDynamicSharedMemorySize, SMEM_GEMM);
    cudaFuncSetAttribute(gemm3bf<1>, cudaFuncAttributeMaxDynamicSharedMemorySize, SMEM_GEMM);
    cudaFuncSetAttribute(gemm3bf<2>, cudaFuncAttributeMaxDynamicSharedMemorySize, SMEM_GEMM);

    // residual init + weight bf16-split conversion
    copy_kernel<<<(MTOT * DM) / 256, 256>>>(x_in, px, MTOT * DM);
    cvt_w<<<(NL * 2 * DI * DM + 255) / 256, 256>>>(in_w,  pwinh, pwinl, NL * 2 * DI * DM);
    cvt_w<<<(NL * 96 * DI + 255) / 256, 256>>>(xp_w,  pwxph, pwxpl, NL * 96 * DI);
    cvt_w<<<(NL * DI * DTR + 255) / 256, 256>>>(dt_w, pwdth, pwdtl, NL * DI * DTR);
    cvt_w<<<(NL * DM * DI + 255) / 256, 256>>>(out_w, pwoh,  pwol,  NL * DM * DI);

    for (int i = 0; i < NL; i++) {
        // layernorm -> bf16 hi/lo
        ln_kernel<1><<<MTOT, 256>>>(px, nullptr, plnh, plnl, ln_g, ln_b);
        // in_proj: [2048,4096] (K=1024)
        gemm3bf<0><<<dim3(32, 16, 1), 256, SMEM_GEMM>>>(
            plnh, plnl, DM,
            pwinh + (size_t)i * 2 * DI * DM, pwinl + (size_t)i * 2 * DI * DM, DM,
            pxz, MTOT, 2 * DI, DM, nullptr);
        // depthwise conv + silu
        conv_silu<<<dim3(DI / 256, SEQ, BATCH), 256>>>(
            pxz, conv_w + (size_t)i * DI * DC, conv_b + (size_t)i * DI,
            pxm, pxmh, pxml);
        // x_proj (N=96): split-K over 8 z-slices of K=256, then reduce
        gemm3bf<0><<<dim3(1, 16, KSPLIT), 256, SMEM_GEMM>>>(
            pxmh, pxml, DI,
            pwxph + (size_t)i * 96 * DI, pwxpl + (size_t)i * 96 * DI, DI,
            pdbcp, MTOT, 96, DI / KSPLIT, nullptr);
        reduce8<<<(MTOT * 96) / 256, 256>>>(pdbcp, pdbc, pdbch, pdbcl);
        // dt_proj + bias + softplus (K=64)
        gemm3bf<2><<<dim3(16, 16, 1), 256, SMEM_GEMM>>>(
            pdbch, pdbcl, 96,
            pwdth + (size_t)i * DI * DTR, pwdtl + (size_t)i * DI * DTR, DTR,
            pdt, MTOT, DI, DTR, dt_b + (size_t)i * DI);
        // selective scan -> y hi/lo
        scan_kernel<<<dim3(DI / 16, BATCH), 256>>>(
            pdt, pxm, pxz, pdbc, A_log + (size_t)i * DI * NS,
            D_sk + (size_t)i * DI, pyh, pyl);
        // out_proj accumulated into residual (K=2048)
        gemm3bf<1><<<dim3(8, 16, 1), 256, SMEM_GEMM>>>(
            pyh, pyl, DI,
            pwoh + (size_t)i * DM * DI, pwol + (size_t)i * DM * DI, DI,
            px, MTOT, DM, DI, nullptr);
    }

    // final layernorm straight into d_out
    ln_kernel<0><<<MTOT, 256>>>(px, out, nullptr, nullptr, ln_g, ln_b);
}

// round 8
// speedup vs baseline: 1.2403x; 1.0558x over previous
#include <cuda_runtime.h>
#include <cuda_bf16.h>
#include <cstdint>
#include <math.h>

#define NL    4
#define BATCH 2
#define SEQ   1024
#define DM    1024
#define DI    2048
#define DTR   64
#define NS    16
#define DC    4
#define MTOT  (BATCH*SEQ)   // 2048
#define KSPLIT 8

typedef __nv_bfloat16 bf16;

// ---------------- scratch (device globals; no allocation allowed) ----------
__device__ float g_x  [MTOT*DM];
__device__ float g_xz [MTOT*2*DI];
__device__ float g_xm [MTOT*DI];
__device__ float g_dbcp[KSPLIT*MTOT*96];
__device__ float g_dbc[MTOT*96];
__device__ float g_dt [MTOT*DI];

__device__ __align__(128) bf16 g_lnh[MTOT*DM];
__device__ __align__(128) bf16 g_lnl[MTOT*DM];
__device__ __align__(128) bf16 g_xmh[MTOT*DI];
__device__ __align__(128) bf16 g_xml[MTOT*DI];
__device__ __align__(128) bf16 g_dbch[MTOT*96];
__device__ __align__(128) bf16 g_dbcl[MTOT*96];
__device__ __align__(128) bf16 g_yh [MTOT*DI];
__device__ __align__(128) bf16 g_yl [MTOT*DI];
__device__ __align__(128) bf16 w_inh [NL*2*DI*DM];
__device__ __align__(128) bf16 w_inl [NL*2*DI*DM];
__device__ __align__(128) bf16 w_xph [NL*96*DI];
__device__ __align__(128) bf16 w_xpl [NL*96*DI];
__device__ __align__(128) bf16 w_dth [NL*DI*DTR];
__device__ __align__(128) bf16 w_dtl [NL*DI*DTR];
__device__ __align__(128) bf16 w_outh[NL*DM*DI];
__device__ __align__(128) bf16 w_outl[NL*DM*DI];

// ---------------- helpers --------------------------------------------------
__device__ __forceinline__ uint32_t smem_u32(const void* p) {
    uint32_t a;
    asm("{ .reg .u64 t; cvta.to.shared.u64 t, %1; cvt.u32.u64 %0, t; }"
        : "=r"(a) : "l"(p));
    return a;
}
#define SW64(x) ((x) ^ (((x) >> 3) & 0x30))

__device__ __forceinline__ void cp16(uint32_t dst, const void* src, int sz) {
    asm volatile("cp.async.cg.shared.global [%0], [%1], 16, %2;"
                 :: "r"(dst), "l"(src), "r"(sz) : "memory");
}
#define CP_COMMIT() asm volatile("cp.async.commit_group;" ::: "memory")
#define CP_WAIT(n)  asm volatile("cp.async.wait_group %0;" :: "n"(n) : "memory")

__device__ __forceinline__ void ldsm4(uint32_t* d, uint32_t addr) {
    asm volatile("ldmatrix.sync.aligned.m8n8.x4.shared.b16 {%0,%1,%2,%3}, [%4];"
        : "=r"(d[0]), "=r"(d[1]), "=r"(d[2]), "=r"(d[3]) : "r"(addr));
}
__device__ __forceinline__ void mma16816(float* c, const uint32_t* a,
                                         uint32_t b0, uint32_t b1) {
    asm volatile(
        "mma.sync.aligned.m16n8k16.row.col.f32.bf16.bf16.f32 "
        "{%0,%1,%2,%3}, {%4,%5,%6,%7}, {%8,%9}, {%0,%1,%2,%3};"
        : "+f"(c[0]), "+f"(c[1]), "+f"(c[2]), "+f"(c[3])
        : "r"(a[0]), "r"(a[1]), "r"(a[2]), "r"(a[3]), "r"(b0), "r"(b1));
}

__device__ __forceinline__ float softplusf(float v) {
    return (v > 20.f) ? v : log1pf(__expf(v));
}
__device__ __forceinline__ void split_bf16(float v, bf16* hp, bf16* lp) {
    bf16 h = __float2bfloat16(v);
    *hp = h;
    *lp = __float2bfloat16(v - __bfloat162float(h));
}

// ---------------- misc kernels --------------------------------------------
__global__ void copy_kernel(const float* __restrict__ a, float* __restrict__ o, int n) {
    int i = blockIdx.x * 256 + threadIdx.x;
    if (i < n) o[i] = a[i];
}
__global__ void cvt_w(const float* __restrict__ src, bf16* __restrict__ hi,
                      bf16* __restrict__ lo, int n) {
    int i = blockIdx.x * 256 + threadIdx.x;
    if (i < n) split_bf16(src[i], hi + i, lo + i);
}

// ---------------- layernorm -----------------------------------------------
template<int BF>
__global__ __launch_bounds__(256)
void ln_kernel(const float* __restrict__ in, float* __restrict__ outp,
               bf16* __restrict__ oh, bf16* __restrict__ ol,
               const float* __restrict__ gw, const float* __restrict__ bw)
{
    int row = blockIdx.x;
    const float* xr = in + (size_t)row * DM;
    int t = threadIdx.x;
    float v[4]; float s = 0.f, s2 = 0.f;
#pragma unroll
    for (int i = 0; i < 4; i++) {
        v[i] = xr[t + i * 256];
        s += v[i];
        s2 = fmaf(v[i], v[i], s2);
    }
#pragma unroll
    for (int o = 16; o > 0; o >>= 1) {
        s  += __shfl_xor_sync(0xffffffffu, s,  o);
        s2 += __shfl_xor_sync(0xffffffffu, s2, o);
    }
    __shared__ float sh[16];
    if ((t & 31) == 0) { sh[t >> 5] = s; sh[(t >> 5) + 8] = s2; }
    __syncthreads();
    float S = 0.f, S2 = 0.f;
#pragma unroll
    for (int i = 0; i < 8; i++) { S += sh[i]; S2 += sh[i + 8]; }
    float mu  = S * (1.f / DM);
    float var = S2 * (1.f / DM) - mu * mu;
    float r   = rsqrtf(var + 1e-5f);
#pragma unroll
    for (int i = 0; i < 4; i++) {
        int c = t + i * 256;
        float val = (v[i] - mu) * r * gw[c] + bw[c];
        if (BF) split_bf16(val, oh + (size_t)row * DM + c, ol + (size_t)row * DM + c);
        else    outp[(size_t)row * DM + c] = val;
    }
}

// ---------------- causal depthwise conv (k=4) + SiLU + bf16 split ---------
__global__ __launch_bounds__(256)
void conv_silu(const float* __restrict__ xz, const float* __restrict__ cw,
               const float* __restrict__ cb, float* __restrict__ xmout,
               bf16* __restrict__ oh, bf16* __restrict__ ol)
{
    int d = blockIdx.x * 256 + threadIdx.x;
    int l = blockIdx.y;
    int b = blockIdx.z;
    float acc = cb[d];
#pragma unroll
    for (int j = 0; j < DC; j++) {
        int lj = l - (DC - 1) + j;
        if (lj >= 0)
            acc = fmaf(cw[d * DC + j], xz[(size_t)(b * SEQ + lj) * (2 * DI) + d], acc);
    }
    float sv = acc / (1.f + __expf(-acc));
    size_t o = (size_t)(b * SEQ + l) * DI + d;
    xmout[o] = sv;
    split_bf16(sv, oh + o, ol + o);
}

// ---------------- reduce split-K partials + bf16 split --------------------
__global__ void reduce8(const float* __restrict__ part, float* __restrict__ outp,
                        bf16* __restrict__ oh, bf16* __restrict__ ol)
{
    int i = blockIdx.x * 256 + threadIdx.x;
    float s = 0.f;
#pragma unroll
    for (int k = 0; k < KSPLIT; k++) s += part[(size_t)k * (MTOT * 96) + i];
    outp[i] = s;
    split_bf16(s, oh + i, ol + i);
}

// ---------------- 3xBF16-split GEMM, cp.async double-buffered -------------
// C[m,n] = sum_k A[m,k]*B[n,k], A=Ah+Al, B=Bh+Bl, terms ah*bh + ah*bl + al*bh.
// Block 128x128, 8 warps (2m x 4n), warp tile 64x32. BK=32, 2 smem stages.
// Stage layout per parity p (32KB): +0 Ah, +8K Al, +16K Bh, +24K Bl;
// each array 128 rows x 64B, SW64-swizzled.
// EPI: 0 = store, 1 = C += acc, 2 = softplus(acc + bias[n])
// gridDim.z > 1 => split-K: z handles K-chunk [z*K,(z+1)*K), writes C + z*M*N.
#define SMEM_GEMM 65536
template<int EPI>
__global__ __launch_bounds__(256, 2)
void gemm3bf(const bf16* __restrict__ Ah, const bf16* __restrict__ Al, int lda,
             const bf16* __restrict__ Bh, const bf16* __restrict__ Bl, int ldb,
             float* __restrict__ C, int M, int N, int K,
             const float* __restrict__ bias)
{
    extern __shared__ char smem[];
    const uint32_t sb = smem_u32(smem);
    const int tid = threadIdx.x, wid = tid >> 5, lane = tid & 31;
    const int m0 = blockIdx.y * 128, n0 = blockIdx.x * 128;
    const long kbeg = (long)blockIdx.z * K;
    if (gridDim.z > 1) C += (size_t)blockIdx.z * M * N;

    const int wm = wid >> 2, wn = wid & 3;   // warp tile origin (64m x 32n)

    // stage loaders: thread (r = tid>>1) loads row r, (tid&1) selects 32B half
    const int r = tid >> 1;
    const int he = (tid & 1) * 16;                 // element offset of half
    const size_t arow_g = (size_t)(m0 + r) * lda + kbeg + he;
    const size_t brow_g = (size_t)(n0 + r) * ldb + kbeg + he;
    const bool bok = (n0 + r) < N;
    const uint32_t rowoff = (uint32_t)(r * 64 + (tid & 1) * 32);
    const uint32_t d0 = SW64(rowoff), d1 = SW64(rowoff + 16);

    // ldmatrix per-lane address pieces
    const int g = lane >> 3, r8 = lane & 7;
    const int arow = wm * 64 + (g & 1) * 8 + r8;   // + mt*16
    const int brow = wn * 32 + (g & 1) * 8 + r8;   // + np*16
    const int khalf = (g >> 1) * 16;               // byte col + kc*32

    float acc[4][4][4];
#pragma unroll
    for (int i = 0; i < 4; i++)
#pragma unroll
        for (int j = 0; j < 4; j++)
#pragma unroll
            for (int q = 0; q < 4; q++) acc[i][j][q] = 0.f;

    const int S = K / 32;

    // stage-issue helper (macro to keep addresses in registers)
#define LOAD_STAGE(s)  do {                                                   \
        uint32_t base = sb + ((s) & 1) * 32768;                               \
        size_t ka = arow_g + (size_t)(s) * 32;                                \
        size_t kb = brow_g + (size_t)(s) * 32;                                \
        const bf16* pbh = bok ? (Bh + kb) : Bh;                               \
        const bf16* pbl = bok ? (Bl + kb) : Bl;                               \
        int bs = bok ? 16 : 0;                                                \
        cp16(base + d0,          Ah + ka,     16);                            \
        cp16(base + d1,          Ah + ka + 8, 16);                            \
        cp16(base + 8192  + d0,  Al + ka,     16);                            \
        cp16(base + 8192  + d1,  Al + ka + 8, 16);                            \
        cp16(base + 16384 + d0,  pbh,         bs);                            \
        cp16(base + 16384 + d1,  pbh + 8,     bs);                            \
        cp16(base + 24576 + d0,  pbl,         bs);                            \
        cp16(base + 24576 + d1,  pbl + 8,     bs);                            \
        CP_COMMIT();                                                          \
    } while (0)

    LOAD_STAGE(0);

    for (int s = 0; s < S; s++) {
        if (s + 1 < S) { LOAD_STAGE(s + 1); CP_WAIT(1); }
        else           { CP_WAIT(0); }
        __syncthreads();

        const uint32_t pb = sb + (s & 1) * 32768;
#pragma unroll
        for (int kc = 0; kc < 2; kc++) {
            uint32_t ah[4][4], al[4][4];
#pragma unroll
            for (int mt = 0; mt < 4; mt++) {
                uint32_t off = SW64((uint32_t)((arow + mt * 16) * 64 + kc * 32 + khalf));
                ldsm4(ah[mt], pb + off);
                ldsm4(al[mt], pb + 8192 + off);
            }
#pragma unroll
            for (int np = 0; np < 2; np++) {
                uint32_t boffs = SW64((uint32_t)((brow + np * 16) * 64 + kc * 32 + khalf));
                uint32_t bh4[4], bl4[4];
                ldsm4(bh4, pb + 16384 + boffs);
                ldsm4(bl4, pb + 24576 + boffs);
#pragma unroll
                for (int mt = 0; mt < 4; mt++) {
                    mma16816(acc[mt][np * 2],     ah[mt], bh4[0], bh4[2]);
                    mma16816(acc[mt][np * 2],     ah[mt], bl4[0], bl4[2]);
                    mma16816(acc[mt][np * 2],     al[mt], bh4[0], bh4[2]);
                    mma16816(acc[mt][np * 2 + 1], ah[mt], bh4[1], bh4[3]);
                    mma16816(acc[mt][np * 2 + 1], ah[mt], bl4[1], bl4[3]);
                    mma16816(acc[mt][np * 2 + 1], al[mt], bh4[1], bh4[3]);
                }
            }
        }
        __syncthreads();   // all warps done with buffer (s&1) before s+2 overwrites
    }

    // epilogue
    const int gid = lane >> 2, tg = lane & 3;
#pragma unroll
    for (int mt = 0; mt < 4; mt++) {
#pragma unroll
        for (int nt = 0; nt < 4; nt++) {
            int gn = n0 + wn * 32 + nt * 8 + tg * 2;
            if (gn < N) {
                int gm = m0 + wm * 64 + mt * 16 + gid;
                float* cp0 = C + (size_t)gm * N + gn;
                float* cp1 = C + (size_t)(gm + 8) * N + gn;
                float2 v0 = make_float2(acc[mt][nt][0], acc[mt][nt][1]);
                float2 v1 = make_float2(acc[mt][nt][2], acc[mt][nt][3]);
                if (EPI == 1) {
                    float2 o0 = *(const float2*)cp0, o1 = *(const float2*)cp1;
                    v0.x += o0.x; v0.y += o0.y; v1.x += o1.x; v1.y += o1.y;
                } else if (EPI == 2) {
                    float b0 = bias[gn], b1 = bias[gn + 1];
                    v0.x = softplusf(v0.x + b0); v0.y = softplusf(v0.y + b1);
                    v1.x = softplusf(v1.x + b0); v1.y = softplusf(v1.y + b1);
                }
                *(float2*)cp0 = v0;
                *(float2*)cp1 = v1;
            }
        }
    }
#undef LOAD_STAGE
}

// ---------------- selective scan (writes bf16 hi/lo of y) -----------------
__global__ __launch_bounds__(256)
void scan_kernel(const float* __restrict__ dt, const float* __restrict__ xm,
                 const float* __restrict__ xz, const float* __restrict__ dbc,
                 const float* __restrict__ A_log, const float* __restrict__ Dsk,
                 bf16* __restrict__ yh, bf16* __restrict__ yl)
{
    int t = threadIdx.x;
    int s = t & 15;
    int d = blockIdx.x * 16 + (t >> 4);
    int b = blockIdx.y;
    float A  = -__expf(A_log[d * NS + s]);
    float Dv = Dsk[d];
    float h  = 0.f;
    for (int l = 0; l < SEQ; l++) {
        int m = b * SEQ + l;
        float dtv = dt[(size_t)m * DI + d];
        float xv  = xm[(size_t)m * DI + d];
        float Bv  = dbc[m * 96 + DTR + s];
        float Cv  = dbc[m * 96 + DTR + NS + s];
        float dA  = __expf(dtv * A);
        h = fmaf(dA, h, dtv * xv * Bv);
        float p = h * Cv;
        p += __shfl_xor_sync(0xffffffffu, p, 1);
        p += __shfl_xor_sync(0xffffffffu, p, 2);
        p += __shfl_xor_sync(0xffffffffu, p, 4);
        p += __shfl_xor_sync(0xffffffffu, p, 8);
        if (s == 0) {
            float zv = xz[(size_t)m * (2 * DI) + DI + d];
            float yv = p + xv * Dv;
            yv *= zv / (1.f + __expf(-zv));
            split_bf16(yv, yh + (size_t)m * DI + d, yl + (size_t)m * DI + d);
        }
    }
}

// ---------------- driver ---------------------------------------------------
extern "C" void kernel_launch(void* const* d_in, const int* in_sizes, int n_in,
                              void* d_out, int out_size)
{
    const float* x_in   = (const float*)d_in[0];
    const float* in_w   = (const float*)d_in[1];
    const float* conv_w = (const float*)d_in[2];
    const float* conv_b = (const float*)d_in[3];
    const float* xp_w   = (const float*)d_in[4];
    const float* dt_w   = (const float*)d_in[5];
    const float* dt_b   = (const float*)d_in[6];
    const float* A_log  = (const float*)d_in[7];
    const float* D_sk   = (const float*)d_in[8];
    const float* out_w  = (const float*)d_in[9];
    const float* ln_g   = (const float*)d_in[10];
    const float* ln_b   = (const float*)d_in[11];
    float* out = (float*)d_out;

    float *px, *pxz, *pxm, *pdbcp, *pdbc, *pdt;
    bf16 *plnh, *plnl, *pxmh, *pxml, *pdbch, *pdbcl, *pyh, *pyl;
    bf16 *pwinh, *pwinl, *pwxph, *pwxpl, *pwdth, *pwdtl, *pwoh, *pwol;
    cudaGetSymbolAddress((void**)&px,    g_x);
    cudaGetSymbolAddress((void**)&pxz,   g_xz);
    cudaGetSymbolAddress((void**)&pxm,   g_xm);
    cudaGetSymbolAddress((void**)&pdbcp, g_dbcp);
    cudaGetSymbolAddress((void**)&pdbc,  g_dbc);
    cudaGetSymbolAddress((void**)&pdt,   g_dt);
    cudaGetSymbolAddress((void**)&plnh,  g_lnh);
    cudaGetSymbolAddress((void**)&plnl,  g_lnl);
    cudaGetSymbolAddress((void**)&pxmh,  g_xmh);
    cudaGetSymbolAddress((void**)&pxml,  g_xml);
    cudaGetSymbolAddress((void**)&pdbch, g_dbch);
    cudaGetSymbolAddress((void**)&pdbcl, g_dbcl);
    cudaGetSymbolAddress((void**)&pyh,   g_yh);
    cudaGetSymbolAddress((void**)&pyl,   g_yl);
    cudaGetSymbolAddress((void**)&pwinh, w_inh);
    cudaGetSymbolAddress((void**)&pwinl, w_inl);
    cudaGetSymbolAddress((void**)&pwxph, w_xph);
    cudaGetSymbolAddress((void**)&pwxpl, w_xpl);
    cudaGetSymbolAddress((void**)&pwdth, w_dth);
    cudaGetSymbolAddress((void**)&pwdtl, w_dtl);
    cudaGetSymbolAddress((void**)&pwoh,  w_outh);
    cudaGetSymbolAddress((void**)&pwol,  w_outl);

    cudaFuncSetAttribute(gemm3bf<0>, cudaFuncAttributeMaxDynamicSharedMemorySize, SMEM_GEMM);
    cudaFuncSetAttribute(gemm3bf<1>, cudaFuncAttributeMaxDynamicSharedMemorySize, SMEM_GEMM);
    cudaFuncSetAttribute(gemm3bf<2>, cudaFuncAttributeMaxDynamicSharedMemorySize, SMEM_GEMM);

    // residual init + weight bf16-split conversion
    copy_kernel<<<(MTOT * DM) / 256, 256>>>(x_in, px, MTOT * DM);
    cvt_w<<<(NL * 2 * DI * DM + 255) / 256, 256>>>(in_w,  pwinh, pwinl, NL * 2 * DI * DM);
    cvt_w<<<(NL * 96 * DI + 255) / 256, 256>>>(xp_w,  pwxph, pwxpl, NL * 96 * DI);
    cvt_w<<<(NL * DI * DTR + 255) / 256, 256>>>(dt_w, pwdth, pwdtl, NL * DI * DTR);
    cvt_w<<<(NL * DM * DI + 255) / 256, 256>>>(out_w, pwoh,  pwol,  NL * DM * DI);

    for (int i = 0; i < NL; i++) {
        // layernorm -> bf16 hi/lo
        ln_kernel<1><<<MTOT, 256>>>(px, nullptr, plnh, plnl, ln_g, ln_b);
        // in_proj: [2048,4096] (K=1024)
        gemm3bf<0><<<dim3(32, 16, 1), 256, SMEM_GEMM>>>(
            plnh, plnl, DM,
            pwinh + (size_t)i * 2 * DI * DM, pwinl + (size_t)i * 2 * DI * DM, DM,
            pxz, MTOT, 2 * DI, DM, nullptr);
        // depthwise conv + silu
        conv_silu<<<dim3(DI / 256, SEQ, BATCH), 256>>>(
            pxz, conv_w + (size_t)i * DI * DC, conv_b + (size_t)i * DI,
            pxm, pxmh, pxml);
        // x_proj (N=96): split-K over 8 z-slices of K=256, then reduce
        gemm3bf<0><<<dim3(1, 16, KSPLIT), 256, SMEM_GEMM>>>(
            pxmh, pxml, DI,
            pwxph + (size_t)i * 96 * DI, pwxpl + (size_t)i * 96 * DI, DI,
            pdbcp, MTOT, 96, DI / KSPLIT, nullptr);
        reduce8<<<(MTOT * 96) / 256, 256>>>(pdbcp, pdbc, pdbch, pdbcl);
        // dt_proj + bias + softplus (K=64)
        gemm3bf<2><<<dim3(16, 16, 1), 256, SMEM_GEMM>>>(
            pdbch, pdbcl, 96,
            pwdth + (size_t)i * DI * DTR, pwdtl + (size_t)i * DI * DTR, DTR,
            pdt, MTOT, DI, DTR, dt_b + (size_t)i * DI);
        // selective scan -> y hi/lo
        scan_kernel<<<dim3(DI / 16, BATCH), 256>>>(
            pdt, pxm, pxz, pdbc, A_log + (size_t)i * DI * NS,
            D_sk + (size_t)i * DI, pyh, pyl);
        // out_proj accumulated into residual (K=2048)
        gemm3bf<1><<<dim3(8, 16, 1), 256, SMEM_GEMM>>>(
            pyh, pyl, DI,
            pwoh + (size_t)i * DM * DI, pwol + (size_t)i * DM * DI, DI,
            px, MTOT, DM, DI, nullptr);
    }

    // final layernorm straight into d_out
    ln_kernel<0><<<MTOT, 256>>>(px, out, nullptr, nullptr, ln_g, ln_b);
}